// round 2
// baseline (speedup 1.0000x reference)
#include <cuda_runtime.h>

// ---------------- problem constants ----------------
#define N_NODES  50000
#define N_EDGES  400000
#define IN_F     128
#define HEADS    4
#define DIM      64
#define HD       256           // HEADS*DIM
#define NGRAPHS  2000
#define NEG_SLOPE 0.2f

// ---------------- device scratch (no allocation allowed) ----------------
__device__ float g_fs[(size_t)N_NODES * HD];      // 51.2 MB
__device__ float g_fd[(size_t)N_NODES * HD];      // 51.2 MB
__device__ float g_e [(size_t)N_EDGES * HEADS];   // logits, then exp
__device__ float g_m [N_NODES * HEADS];           // segment max
__device__ float g_den[N_NODES * HEADS];          // softmax denom
__device__ float g_rst[(size_t)N_NODES * HD];     // aggregated messages
__device__ float g_hsum[NGRAPHS * DIM];
__device__ float g_cnt [NGRAPHS];

// ---------------- helpers ----------------
__device__ __forceinline__ void atomicMaxF(float* addr, float v) {
    if (v >= 0.0f) atomicMax((int*)addr, __float_as_int(v));
    else           atomicMin((unsigned int*)addr, __float_as_uint(v));
}

__device__ __forceinline__ float lrelu(float x) {
    return x > 0.0f ? x : NEG_SLOPE * x;
}

// ---------------- init: zero/neg-inf scratch ----------------
__global__ void k_init() {
    size_t i = (size_t)blockIdx.x * blockDim.x + threadIdx.x;
    size_t stride = (size_t)gridDim.x * blockDim.x;
    const float NEG_INF = __int_as_float(0xff800000);
    for (size_t j = i; j < (size_t)N_NODES * HD; j += stride) g_rst[j] = 0.0f;
    for (size_t j = i; j < (size_t)N_NODES * HEADS; j += stride) { g_m[j] = NEG_INF; g_den[j] = 0.0f; }
    for (size_t j = i; j < (size_t)NGRAPHS * DIM; j += stride) g_hsum[j] = 0.0f;
    for (size_t j = i; j < (size_t)NGRAPHS; j += stride) g_cnt[j] = 0.0f;
}

// ---------------- SGEMM: fs = atom@Wsrc+b, fd = atom@Wdst+b ----------------
// grid.x tiles M (64 rows), grid.y in {0,1}=fs halves, {2,3}=fd halves (128 cols each)
#define BM 64
#define BN 128
#define BK 16
__global__ __launch_bounds__(256) void k_gemm(
    const float* __restrict__ atom,
    const float* __restrict__ Wsrc, const float* __restrict__ bsrc,
    const float* __restrict__ Wdst, const float* __restrict__ bdst)
{
    __shared__ float As[BK][BM];
    __shared__ float Bs[BK][BN];

    const int by   = blockIdx.y;                       // 0..3
    const float* W    = (by < 2) ? Wsrc : Wdst;
    const float* bias = (by < 2) ? bsrc : bdst;
    float* out        = (by < 2) ? g_fs : g_fd;
    const int n0   = (by & 1) * BN;
    const int row0 = blockIdx.x * BM;

    const int tid = threadIdx.x;     // 256 threads
    const int tx  = tid & 15;        // 16 col-groups of 8
    const int ty  = tid >> 4;        // 16 row-groups of 4

    float acc[4][8];
#pragma unroll
    for (int i = 0; i < 4; i++)
#pragma unroll
        for (int j = 0; j < 8; j++) acc[i][j] = 0.0f;

    const int am  = tid >> 2;          // 0..63
    const int ak4 = (tid & 3) * 4;     // 0,4,8,12

    for (int k0 = 0; k0 < IN_F; k0 += BK) {
        // A tile: 64 rows x 16 k, one float4 per thread, stored transposed
        float4 av = make_float4(0.f, 0.f, 0.f, 0.f);
        int arow = row0 + am;
        if (arow < N_NODES)
            av = *(const float4*)(atom + (size_t)arow * IN_F + k0 + ak4);
        As[ak4 + 0][am] = av.x;
        As[ak4 + 1][am] = av.y;
        As[ak4 + 2][am] = av.z;
        As[ak4 + 3][am] = av.w;

        // B tile: 16 k x 128 cols, two float4 per thread, coalesced
#pragma unroll
        for (int it = 0; it < 2; it++) {
            int idx = tid + it * 256;
            int bk  = idx >> 5;             // 0..15
            int bn4 = (idx & 31) * 4;       // 0..124
            float4 bv = *(const float4*)(W + (size_t)(k0 + bk) * HD + n0 + bn4);
            *(float4*)(&Bs[bk][bn4]) = bv;
        }
        __syncthreads();

#pragma unroll
        for (int k = 0; k < BK; k++) {
            float a[4], b[8];
#pragma unroll
            for (int i = 0; i < 4; i++) a[i] = As[k][ty * 4 + i];
#pragma unroll
            for (int j = 0; j < 8; j++) b[j] = Bs[k][tx * 8 + j];
#pragma unroll
            for (int i = 0; i < 4; i++)
#pragma unroll
                for (int j = 0; j < 8; j++)
                    acc[i][j] = fmaf(a[i], b[j], acc[i][j]);
        }
        __syncthreads();
    }

#pragma unroll
    for (int i = 0; i < 4; i++) {
        int row = row0 + ty * 4 + i;
        if (row < N_NODES) {
            float* op = out + (size_t)row * HD + n0 + tx * 8;
#pragma unroll
            for (int j = 0; j < 8; j++)
                op[j] = acc[i][j] + bias[n0 + tx * 8 + j];
        }
    }
}

// ---------------- edge logits + segment max (warp per edge) ----------------
__global__ __launch_bounds__(256) void k_logits(
    const int* __restrict__ src, const int* __restrict__ dst,
    const float* __restrict__ attn)
{
    int w = (int)(((size_t)blockIdx.x * blockDim.x + threadIdx.x) >> 5);
    if (w >= N_EDGES) return;
    int lane = threadIdx.x & 31;
    int s = src[w], d = dst[w];
    int base = lane * 8;                   // 8 contiguous floats, within one head

    const float4* pfs = (const float4*)(g_fs + (size_t)s * HD + base);
    const float4* pfd = (const float4*)(g_fd + (size_t)d * HD + base);
    const float4* pw  = (const float4*)(attn + base);
    float4 a0 = pfs[0], a1 = pfs[1];
    float4 b0 = pfd[0], b1 = pfd[1];
    float4 w0 = pw[0],  w1 = pw[1];

    float sum;
    sum  = lrelu(a0.x + b0.x) * w0.x;
    sum += lrelu(a0.y + b0.y) * w0.y;
    sum += lrelu(a0.z + b0.z) * w0.z;
    sum += lrelu(a0.w + b0.w) * w0.w;
    sum += lrelu(a1.x + b1.x) * w1.x;
    sum += lrelu(a1.y + b1.y) * w1.y;
    sum += lrelu(a1.z + b1.z) * w1.z;
    sum += lrelu(a1.w + b1.w) * w1.w;

    // reduce across the 8 lanes of this head
    sum += __shfl_xor_sync(0xFFFFFFFFu, sum, 1);
    sum += __shfl_xor_sync(0xFFFFFFFFu, sum, 2);
    sum += __shfl_xor_sync(0xFFFFFFFFu, sum, 4);

    if ((lane & 7) == 0) {
        int h = lane >> 3;
        g_e[(size_t)w * HEADS + h] = sum;
        atomicMaxF(&g_m[d * HEADS + h], sum);
    }
}

// ---------------- exp + segment sum denom (thread per edge-head) ----------------
__global__ __launch_bounds__(256) void k_exp(const int* __restrict__ dst)
{
    int idx = (int)((size_t)blockIdx.x * blockDim.x + threadIdx.x);
    if (idx >= N_EDGES * HEADS) return;
    int e = idx >> 2, h = idx & 3;
    int d = dst[e];
    float ex = expf(g_e[idx] - g_m[d * HEADS + h]);
    g_e[idx] = ex;
    atomicAdd(&g_den[d * HEADS + h], ex);
}

// ---------------- alpha + score + message scatter (warp per edge) ----------------
__global__ __launch_bounds__(256) void k_scatter(
    const int* __restrict__ src, const int* __restrict__ dst,
    float* __restrict__ score)
{
    int w = (int)(((size_t)blockIdx.x * blockDim.x + threadIdx.x) >> 5);
    if (w >= N_EDGES) return;
    int lane = threadIdx.x & 31;
    int s = src[w], d = dst[w];
    int h = lane >> 3;

    float ex  = g_e[(size_t)w * HEADS + h];
    float den = g_den[d * HEADS + h];
    float alpha = ex / den;

    if ((lane & 7) == 0)
        score[(size_t)w * HEADS + h] = alpha;

    int base = lane * 8;
    const float4* pf = (const float4*)(g_fs + (size_t)s * HD + base);
    float4 a = pf[0], b = pf[1];
    float4 v0 = make_float4(a.x * alpha, a.y * alpha, a.z * alpha, a.w * alpha);
    float4 v1 = make_float4(b.x * alpha, b.y * alpha, b.z * alpha, b.w * alpha);
    atomicAdd((float4*)(g_rst + (size_t)d * HD + base),     v0);
    atomicAdd((float4*)(g_rst + (size_t)d * HD + base + 4), v1);
}

// ---------------- head mean + graph-pool accumulate ----------------
__global__ __launch_bounds__(256) void k_node(
    const int* __restrict__ gid, float* __restrict__ x1)
{
    int idx = (int)((size_t)blockIdx.x * blockDim.x + threadIdx.x);
    if (idx >= N_NODES * DIM) return;
    int n = idx >> 6, dd = idx & 63;
    const float* r = g_rst + (size_t)n * HD;
    float v = 0.25f * (r[dd] + r[64 + dd] + r[128 + dd] + r[192 + dd]);
    x1[idx] = v;
    int g = gid[n];
    atomicAdd(&g_hsum[g * DIM + dd], v);
    if (dd == 0) atomicAdd(&g_cnt[g], 1.0f);
}

// ---------------- graph mean finalize ----------------
__global__ __launch_bounds__(256) void k_final(float* __restrict__ hout)
{
    int idx = (int)((size_t)blockIdx.x * blockDim.x + threadIdx.x);
    if (idx >= NGRAPHS * DIM) return;
    int g = idx >> 6;
    hout[idx] = g_hsum[idx] / fmaxf(g_cnt[g], 1.0f);
}

// ---------------- launcher ----------------
extern "C" void kernel_launch(void* const* d_in, const int* in_sizes, int n_in,
                              void* d_out, int out_size)
{
    (void)in_sizes; (void)n_in; (void)out_size;

    const float* atom = (const float*)d_in[0];
    const float* Wsrc = (const float*)d_in[1];
    const float* bsrc = (const float*)d_in[2];
    const float* Wdst = (const float*)d_in[3];
    const float* bdst = (const float*)d_in[4];
    const float* attn = (const float*)d_in[5];
    const int*   src  = (const int*)d_in[6];
    const int*   dst  = (const int*)d_in[7];
    const int*   gid  = (const int*)d_in[8];

    float* out   = (float*)d_out;
    float* x1    = out;                                   // 50000*64
    float* hout  = out + (size_t)N_NODES * DIM;           // 2000*64
    float* score = hout + (size_t)NGRAPHS * DIM;          // 400000*4

    k_init<<<2048, 256>>>();

    dim3 ggrid((N_NODES + BM - 1) / BM, 4);
    k_gemm<<<ggrid, 256>>>(atom, Wsrc, bsrc, Wdst, bdst);

    int logit_blocks = (N_EDGES * 32 + 255) / 256;        // warp per edge
    k_logits<<<logit_blocks, 256>>>(src, dst, attn);

    k_exp<<<(N_EDGES * HEADS + 255) / 256, 256>>>(dst);

    k_scatter<<<logit_blocks, 256>>>(src, dst, score);

    k_node<<<(N_NODES * DIM + 255) / 256, 256>>>(gid, x1);

    k_final<<<(NGRAPHS * DIM + 255) / 256, 256>>>(hout);
}

// round 3
// speedup vs baseline: 1.2697x; 1.2697x over previous
#include <cuda_runtime.h>

// ---------------- problem constants ----------------
#define N_NODES  50000
#define N_EDGES  400000
#define IN_F     128
#define HEADS    4
#define DIM      64
#define HD       256           // HEADS*DIM
#define NGRAPHS  2000
#define NEG_SLOPE 0.2f
#define SCAN_NB  196           // ceil(50000/256)

// ---------------- device scratch (no allocation allowed) ----------------
__device__ float g_fs[(size_t)N_NODES * HD];      // 51.2 MB
__device__ float g_fd[(size_t)N_NODES * HD];      // 51.2 MB
__device__ float g_e [(size_t)N_EDGES * HEADS];   // logits
__device__ float g_m [N_NODES * HEADS];           // per-node max (for score pass)
__device__ float g_den[N_NODES * HEADS];          // per-node denom (for score pass)
__device__ float g_hsum[NGRAPHS * DIM];
__device__ float g_cnt [NGRAPHS];
__device__ int   g_deg[N_NODES];
__device__ int   g_cur[N_NODES];
__device__ int   g_off[N_NODES];
__device__ int   g_eid[N_EDGES];
__device__ int   g_blksum[SCAN_NB];

__device__ __forceinline__ float lrelu(float x) {
    return x > 0.0f ? x : NEG_SLOPE * x;
}

// ---------------- init: zero small scratch ----------------
__global__ void k_init() {
    int i = blockIdx.x * blockDim.x + threadIdx.x;
    int stride = gridDim.x * blockDim.x;
    for (int j = i; j < NGRAPHS * DIM; j += stride) g_hsum[j] = 0.0f;
    for (int j = i; j < NGRAPHS; j += stride) g_cnt[j] = 0.0f;
    for (int j = i; j < N_NODES; j += stride) { g_deg[j] = 0; g_cur[j] = 0; }
}

// ---------------- SGEMM: fs = atom@Wsrc+b, fd = atom@Wdst+b ----------------
#define BM 64
#define BN 128
#define BK 16
__global__ __launch_bounds__(256) void k_gemm(
    const float* __restrict__ atom,
    const float* __restrict__ Wsrc, const float* __restrict__ bsrc,
    const float* __restrict__ Wdst, const float* __restrict__ bdst)
{
    __shared__ float As[BK][BM];
    __shared__ float Bs[BK][BN];

    const int by   = blockIdx.y;                       // 0..3
    const float* W    = (by < 2) ? Wsrc : Wdst;
    const float* bias = (by < 2) ? bsrc : bdst;
    float* out        = (by < 2) ? g_fs : g_fd;
    const int n0   = (by & 1) * BN;
    const int row0 = blockIdx.x * BM;

    const int tid = threadIdx.x;     // 256 threads
    const int tx  = tid & 15;
    const int ty  = tid >> 4;

    float acc[4][8];
#pragma unroll
    for (int i = 0; i < 4; i++)
#pragma unroll
        for (int j = 0; j < 8; j++) acc[i][j] = 0.0f;

    const int am  = tid >> 2;
    const int ak4 = (tid & 3) * 4;

    for (int k0 = 0; k0 < IN_F; k0 += BK) {
        float4 av = make_float4(0.f, 0.f, 0.f, 0.f);
        int arow = row0 + am;
        if (arow < N_NODES)
            av = *(const float4*)(atom + (size_t)arow * IN_F + k0 + ak4);
        As[ak4 + 0][am] = av.x;
        As[ak4 + 1][am] = av.y;
        As[ak4 + 2][am] = av.z;
        As[ak4 + 3][am] = av.w;

#pragma unroll
        for (int it = 0; it < 2; it++) {
            int idx = tid + it * 256;
            int bk  = idx >> 5;
            int bn4 = (idx & 31) * 4;
            float4 bv = *(const float4*)(W + (size_t)(k0 + bk) * HD + n0 + bn4);
            *(float4*)(&Bs[bk][bn4]) = bv;
        }
        __syncthreads();

#pragma unroll
        for (int k = 0; k < BK; k++) {
            float a[4], b[8];
#pragma unroll
            for (int i = 0; i < 4; i++) a[i] = As[k][ty * 4 + i];
#pragma unroll
            for (int j = 0; j < 8; j++) b[j] = Bs[k][tx * 8 + j];
#pragma unroll
            for (int i = 0; i < 4; i++)
#pragma unroll
                for (int j = 0; j < 8; j++)
                    acc[i][j] = fmaf(a[i], b[j], acc[i][j]);
        }
        __syncthreads();
    }

#pragma unroll
    for (int i = 0; i < 4; i++) {
        int row = row0 + ty * 4 + i;
        if (row < N_NODES) {
            float* op = out + (size_t)row * HD + n0 + tx * 8;
#pragma unroll
            for (int j = 0; j < 8; j++)
                op[j] = acc[i][j] + bias[n0 + tx * 8 + j];
        }
    }
}

// ---------------- CSR build ----------------
__global__ __launch_bounds__(256) void k_hist(const int* __restrict__ dst) {
    int e = blockIdx.x * blockDim.x + threadIdx.x;
    if (e < N_EDGES) atomicAdd(&g_deg[dst[e]], 1);
}

__global__ __launch_bounds__(256) void k_scan1() {
    __shared__ int sh[256];
    int i = blockIdx.x * 256 + threadIdx.x;
    int v = (i < N_NODES) ? g_deg[i] : 0;
    sh[threadIdx.x] = v;
    __syncthreads();
    for (int d = 1; d < 256; d <<= 1) {
        int t = (threadIdx.x >= d) ? sh[threadIdx.x - d] : 0;
        __syncthreads();
        sh[threadIdx.x] += t;
        __syncthreads();
    }
    if (threadIdx.x == 255) g_blksum[blockIdx.x] = sh[255];
}

__global__ __launch_bounds__(256) void k_scan2() {
    __shared__ int sh[256];
    int v = (threadIdx.x < SCAN_NB) ? g_blksum[threadIdx.x] : 0;
    sh[threadIdx.x] = v;
    __syncthreads();
    for (int d = 1; d < 256; d <<= 1) {
        int t = (threadIdx.x >= d) ? sh[threadIdx.x - d] : 0;
        __syncthreads();
        sh[threadIdx.x] += t;
        __syncthreads();
    }
    if (threadIdx.x < SCAN_NB) g_blksum[threadIdx.x] = sh[threadIdx.x] - v;  // exclusive
}

__global__ __launch_bounds__(256) void k_scan3() {
    __shared__ int sh[256];
    int i = blockIdx.x * 256 + threadIdx.x;
    int v = (i < N_NODES) ? g_deg[i] : 0;
    sh[threadIdx.x] = v;
    __syncthreads();
    for (int d = 1; d < 256; d <<= 1) {
        int t = (threadIdx.x >= d) ? sh[threadIdx.x - d] : 0;
        __syncthreads();
        sh[threadIdx.x] += t;
        __syncthreads();
    }
    if (i < N_NODES) g_off[i] = g_blksum[blockIdx.x] + sh[threadIdx.x] - v;
}

__global__ __launch_bounds__(256) void k_fill(const int* __restrict__ dst) {
    int e = blockIdx.x * blockDim.x + threadIdx.x;
    if (e >= N_EDGES) return;
    int d = dst[e];
    int pos = atomicAdd(&g_cur[d], 1);
    g_eid[g_off[d] + pos] = e;
}

// ---------------- fused per-node online-softmax aggregation ----------------
// warp per node: logits + softmax + weighted gather + head-mean + graph pool
__global__ __launch_bounds__(256) void k_agg(
    const int* __restrict__ src, const float* __restrict__ attn,
    const int* __restrict__ gid, float* __restrict__ x1)
{
    int warp = (blockIdx.x * blockDim.x + threadIdx.x) >> 5;
    if (warp >= N_NODES) return;
    int n = warp;
    int lane = threadIdx.x & 31;
    int base = lane * 8;                // 8 contiguous floats within one head
    int h = lane >> 3;

    // per-node constants
    float4 fd0 = *(const float4*)(g_fd + (size_t)n * HD + base);
    float4 fd1 = *(const float4*)(g_fd + (size_t)n * HD + base + 4);
    float4 aw0 = __ldg((const float4*)(attn + base));
    float4 aw1 = __ldg((const float4*)(attn + base + 4));

    int deg = g_deg[n];
    int off = g_off[n];

    float m = __int_as_float(0xff800000);   // -inf
    float den = 0.0f;
    float acc[8];
#pragma unroll
    for (int j = 0; j < 8; j++) acc[j] = 0.0f;

    for (int i = 0; i < deg; i++) {
        int e_id = g_eid[off + i];
        int s = src[e_id];
        const float4* pfs = (const float4*)(g_fs + (size_t)s * HD + base);
        float4 a0 = pfs[0], a1 = pfs[1];

        float e_val;
        e_val  = lrelu(a0.x + fd0.x) * aw0.x;
        e_val += lrelu(a0.y + fd0.y) * aw0.y;
        e_val += lrelu(a0.z + fd0.z) * aw0.z;
        e_val += lrelu(a0.w + fd0.w) * aw0.w;
        e_val += lrelu(a1.x + fd1.x) * aw1.x;
        e_val += lrelu(a1.y + fd1.y) * aw1.y;
        e_val += lrelu(a1.z + fd1.z) * aw1.z;
        e_val += lrelu(a1.w + fd1.w) * aw1.w;
        // reduce across 8 lanes of this head
        e_val += __shfl_xor_sync(0xFFFFFFFFu, e_val, 1);
        e_val += __shfl_xor_sync(0xFFFFFFFFu, e_val, 2);
        e_val += __shfl_xor_sync(0xFFFFFFFFu, e_val, 4);

        if ((lane & 7) == 0)
            g_e[(size_t)e_id * HEADS + h] = e_val;

        // online softmax update (per head, replicated within head group)
        float m_new = fmaxf(m, e_val);
        float scale = expf(m - m_new);      // exp(-inf)=0 on first edge
        float ex    = expf(e_val - m_new);
        den = den * scale + ex;
        acc[0] = acc[0] * scale + ex * a0.x;
        acc[1] = acc[1] * scale + ex * a0.y;
        acc[2] = acc[2] * scale + ex * a0.z;
        acc[3] = acc[3] * scale + ex * a0.w;
        acc[4] = acc[4] * scale + ex * a1.x;
        acc[5] = acc[5] * scale + ex * a1.y;
        acc[6] = acc[6] * scale + ex * a1.z;
        acc[7] = acc[7] * scale + ex * a1.w;
        m = m_new;
    }

    if (deg > 0 && (lane & 7) == 0) {
        g_m  [n * HEADS + h] = m;
        g_den[n * HEADS + h] = den;
    }

    // rst = acc/den ; head-mean via shfl over lane bits 3,4
    float inv = (den > 0.0f) ? (1.0f / den) : 0.0f;
    float r[8];
#pragma unroll
    for (int j = 0; j < 8; j++) {
        r[j] = acc[j] * inv;
        r[j] += __shfl_xor_sync(0xFFFFFFFFu, r[j], 8);
        r[j] += __shfl_xor_sync(0xFFFFFFFFu, r[j], 16);
        r[j] *= 0.25f;
    }

    int g = gid[n];
    if (lane < 8) {
        float4 v0 = make_float4(r[0], r[1], r[2], r[3]);
        float4 v1 = make_float4(r[4], r[5], r[6], r[7]);
        float* xp = x1 + (size_t)n * DIM + lane * 8;
        *(float4*)(xp)     = v0;
        *(float4*)(xp + 4) = v1;
        atomicAdd((float4*)(g_hsum + (size_t)g * DIM + lane * 8),     v0);
        atomicAdd((float4*)(g_hsum + (size_t)g * DIM + lane * 8 + 4), v1);
    }
    if (lane == 0) atomicAdd(&g_cnt[g], 1.0f);
}

// ---------------- score: alpha = exp(e - m)/den ----------------
__global__ __launch_bounds__(256) void k_score(
    const int* __restrict__ dst, float* __restrict__ score)
{
    int idx = blockIdx.x * blockDim.x + threadIdx.x;
    if (idx >= N_EDGES * HEADS) return;
    int e = idx >> 2, h = idx & 3;
    int d = dst[e];
    float alpha = expf(g_e[idx] - g_m[d * HEADS + h]) / g_den[d * HEADS + h];
    score[idx] = alpha;
}

// ---------------- graph mean finalize ----------------
__global__ __launch_bounds__(256) void k_final(float* __restrict__ hout)
{
    int idx = blockIdx.x * blockDim.x + threadIdx.x;
    if (idx >= NGRAPHS * DIM) return;
    int g = idx >> 6;
    hout[idx] = g_hsum[idx] / fmaxf(g_cnt[g], 1.0f);
}

// ---------------- launcher ----------------
extern "C" void kernel_launch(void* const* d_in, const int* in_sizes, int n_in,
                              void* d_out, int out_size)
{
    (void)in_sizes; (void)n_in; (void)out_size;

    const float* atom = (const float*)d_in[0];
    const float* Wsrc = (const float*)d_in[1];
    const float* bsrc = (const float*)d_in[2];
    const float* Wdst = (const float*)d_in[3];
    const float* bdst = (const float*)d_in[4];
    const float* attn = (const float*)d_in[5];
    const int*   src  = (const int*)d_in[6];
    const int*   dst  = (const int*)d_in[7];
    const int*   gid  = (const int*)d_in[8];

    float* out   = (float*)d_out;
    float* x1    = out;                                   // 50000*64
    float* hout  = out + (size_t)N_NODES * DIM;           // 2000*64
    float* score = hout + (size_t)NGRAPHS * DIM;          // 400000*4

    k_init<<<256, 256>>>();

    dim3 ggrid((N_NODES + BM - 1) / BM, 4);
    k_gemm<<<ggrid, 256>>>(atom, Wsrc, bsrc, Wdst, bdst);

    int eblocks = (N_EDGES + 255) / 256;
    k_hist<<<eblocks, 256>>>(dst);
    k_scan1<<<SCAN_NB, 256>>>();
    k_scan2<<<1, 256>>>();
    k_scan3<<<SCAN_NB, 256>>>();
    k_fill<<<eblocks, 256>>>(dst);

    k_agg<<<(N_NODES * 32 + 255) / 256, 256>>>(src, attn, gid, x1);

    k_score<<<(N_EDGES * HEADS + 255) / 256, 256>>>(dst, score);

    k_final<<<(NGRAPHS * DIM + 255) / 256, 256>>>(hout);
}

// round 6
// speedup vs baseline: 2.1687x; 1.7081x over previous
#include <cuda_runtime.h>
#include <cuda_bf16.h>
#include <cstdint>

// ---------------- problem constants ----------------
#define N_NODES  50000
#define N_EDGES  400000
#define IN_F     128
#define HEADS    4
#define DIM      64
#define HD       256           // HEADS*DIM
#define NGRAPHS  2000
#define NEG_SLOPE 0.2f
#define SCAN_NB  196           // ceil(50000/256)
#define KEXT     384           // 3 * IN_F (bf16 split terms)

// ---------------- device scratch (no allocation allowed) ----------------
__device__ float g_fs[(size_t)N_NODES * HD];      // 51.2 MB
__device__ float g_fd[(size_t)N_NODES * HD];      // 51.2 MB
__device__ float g_e [(size_t)N_EDGES * HEADS];   // logits
__device__ float g_m [N_NODES * HEADS];
__device__ float g_den[N_NODES * HEADS];
__device__ float g_hsum[NGRAPHS * DIM];
__device__ float g_cnt [NGRAPHS];
__device__ int   g_deg[N_NODES];
__device__ int   g_cur[N_NODES];
__device__ int   g_off[N_NODES];
__device__ int   g_eid[N_EDGES];
__device__ int   g_blksum[SCAN_NB];
// B_ext images: [mat][kext=384][n=256] bf16 ; kext<256 -> hi(W), >=256 -> lo(W)
__device__ __align__(16) __nv_bfloat16 g_Bext[2 * KEXT * HD];

__device__ __forceinline__ float lrelu(float x) {
    return x > 0.0f ? x : NEG_SLOPE * x;
}

__device__ __forceinline__ uint32_t smem_u32(const void* p) {
    uint32_t a;
    asm("{ .reg .u64 t; cvta.to.shared.u64 t, %1; cvt.u32.u64 %0, t; }" : "=r"(a) : "l"(p));
    return a;
}

// A smem: 128 rows x 256 bf16 cols (cols 0-127 = hi, 128-255 = lo), 512 B/row
__device__ __forceinline__ uint32_t a_off(int r, int c) {
    int chunk = (c >> 3) ^ (r & 7);
    return (uint32_t)r * 512u + (uint32_t)chunk * 16u + (uint32_t)(c & 7) * 2u;
}
// B smem: 32 k-rows x 128 bf16 cols, 256 B/row
__device__ __forceinline__ uint32_t b_off(int k, int n) {
    int chunk = (n >> 3) ^ (k & 7);
    return (uint32_t)k * 256u + (uint32_t)chunk * 16u + (uint32_t)(n & 7) * 2u;
}

// ---------------- init ----------------
__global__ void k_init() {
    int i = blockIdx.x * blockDim.x + threadIdx.x;
    int stride = gridDim.x * blockDim.x;
    for (int j = i; j < NGRAPHS * DIM; j += stride) g_hsum[j] = 0.0f;
    for (int j = i; j < NGRAPHS; j += stride) g_cnt[j] = 0.0f;
    for (int j = i; j < N_NODES; j += stride) { g_deg[j] = 0; g_cur[j] = 0; }
}

// ---------------- prep: B_ext = [Whi | Whi | Wlo] over kext ----------------
__global__ __launch_bounds__(256) void k_prepB(
    const float* __restrict__ Wsrc, const float* __restrict__ Wdst)
{
    int idx = blockIdx.x * blockDim.x + threadIdx.x;   // 2*384*256 = 196608
    if (idx >= 2 * KEXT * HD) return;
    int mat  = idx / (KEXT * HD);
    int r    = idx % (KEXT * HD);
    int kext = r >> 8;
    int n    = r & 255;
    int k    = (kext < 2 * IN_F) ? (kext & (IN_F - 1)) : (kext - 2 * IN_F);
    const float* W = mat ? Wdst : Wsrc;
    float v = W[(size_t)k * HD + n];
    __nv_bfloat16 hi = __float2bfloat16(v);
    __nv_bfloat16 out = (kext < 2 * IN_F) ? hi : __float2bfloat16(v - __bfloat162float(hi));
    g_Bext[idx] = out;
}

// ---------------- bf16 mma.sync GEMM ----------------
// block 256 thr, tile 128(M) x 128(N); K_ext = 384 in 12 chunks of 32
// grid = (391, 4): blockIdx.y = mat*2 + nhalf
#define SM_A_BYTES 65536
#define SM_B_BYTES 8192
#define SM_TOT (SM_A_BYTES + SM_B_BYTES)

__global__ __launch_bounds__(256) void k_mgemm(
    const float* __restrict__ atom,
    const float* __restrict__ bsrc, const float* __restrict__ bdst)
{
    extern __shared__ char smem[];
    const uint32_t sA = smem_u32(smem);
    const uint32_t sB = sA + SM_A_BYTES;

    const int tid  = threadIdx.x;
    const int lane = tid & 31;
    const int wid  = tid >> 5;
    const int mat  = blockIdx.y >> 1;
    const int nh   = blockIdx.y & 1;
    const int row0 = blockIdx.x * 128;

    // ---- A: load 128 rows x 128 fp32, convert to hi/lo bf16 into smem ----
    {
        int ar = tid >> 1;
        int c0 = (tid & 1) * 64;
        bool valid = (row0 + ar) < N_NODES;
        const float4* arow = (const float4*)(atom + (size_t)(row0 + ar) * IN_F + c0);
#pragma unroll
        for (int i = 0; i < 16; i++) {
            float4 v = valid ? arow[i] : make_float4(0.f, 0.f, 0.f, 0.f);
            int c = c0 + i * 4;
            __nv_bfloat162 h0 = __float22bfloat162_rn(make_float2(v.x, v.y));
            __nv_bfloat162 h1 = __float22bfloat162_rn(make_float2(v.z, v.w));
            float2 f0 = __bfloat1622float2(h0);
            float2 f1 = __bfloat1622float2(h1);
            __nv_bfloat162 l0 = __float22bfloat162_rn(make_float2(v.x - f0.x, v.y - f0.y));
            __nv_bfloat162 l1 = __float22bfloat162_rn(make_float2(v.z - f1.x, v.w - f1.y));
            uint2 hp, lp;
            hp.x = *(uint32_t*)&h0; hp.y = *(uint32_t*)&h1;
            lp.x = *(uint32_t*)&l0; lp.y = *(uint32_t*)&l1;
            *(uint2*)(smem + a_off(ar, c))       = hp;      // hi at cols [0,128)
            *(uint2*)(smem + a_off(ar, 128 + c)) = lp;      // lo at cols [128,256)
        }
    }
    __syncthreads();

    // ---- warp tiling ----
    const int wr = wid >> 1;               // 0..3
    const int wc = wid & 1;                // 0..1
    const int mbase = wr * 32;
    const int nbase = wc * 64;

    float acc[2][8][4];
#pragma unroll
    for (int a = 0; a < 2; a++)
#pragma unroll
        for (int b = 0; b < 8; b++)
#pragma unroll
            for (int c = 0; c < 4; c++) acc[a][b][c] = 0.0f;

    const __nv_bfloat16* Bg = g_Bext + (size_t)mat * KEXT * HD;
    const int kr = tid >> 3;               // 0..31
    const int ch = tid & 7;                // 0..7
    // full 32x128 B tile = 8192 B -> two uint4 per thread
    const uint32_t bso0 = SM_A_BYTES + b_off(kr, ch * 8);
    const uint32_t bso1 = SM_A_BYTES + b_off(kr, 64 + ch * 8);

    // ldmatrix lane addressing (precomputed pieces)
    const int a_r  = lane & 15;
    const int a_c8 = (lane >> 4) << 3;
    const int b_kr = (lane & 7) + (((lane >> 3) & 1) << 3);
    const int b_n8 = (lane >> 4) << 3;

    for (int it = 0; it < 12; it++) {
        const int kk = it * 32;
        // stage full B chunk (32 B / thread)
        const __nv_bfloat16* brow = Bg + (size_t)(kk + kr) * HD + nh * 128;
        uint4 bv0 = *(const uint4*)(brow + ch * 8);
        uint4 bv1 = *(const uint4*)(brow + 64 + ch * 8);
        __syncthreads();                   // prev iteration's reads done
        *(uint4*)(smem + bso0) = bv0;
        *(uint4*)(smem + bso1) = bv1;
        __syncthreads();                   // B tile ready

        const int term = kk >> 7;
        const int acolb = (term == 1) ? (128 + (kk & 127)) : (kk & 127);

#pragma unroll
        for (int ks = 0; ks < 32; ks += 16) {
            // A fragments (2 m-tiles)
            uint32_t af[2][4];
#pragma unroll
            for (int mi = 0; mi < 2; mi++) {
                uint32_t addr = sA + a_off(mbase + mi * 16 + a_r, acolb + ks + a_c8);
                asm volatile("ldmatrix.sync.aligned.m8n8.x4.shared.b16 {%0,%1,%2,%3}, [%4];"
                             : "=r"(af[mi][0]), "=r"(af[mi][1]), "=r"(af[mi][2]), "=r"(af[mi][3])
                             : "r"(addr));
            }
            // B fragments (4 x 16-wide n-tiles)
            uint32_t bf[4][4];
#pragma unroll
            for (int ni = 0; ni < 4; ni++) {
                uint32_t addr = sB + b_off(ks + b_kr, nbase + ni * 16 + b_n8);
                asm volatile("ldmatrix.sync.aligned.m8n8.x4.trans.shared.b16 {%0,%1,%2,%3}, [%4];"
                             : "=r"(bf[ni][0]), "=r"(bf[ni][1]), "=r"(bf[ni][2]), "=r"(bf[ni][3])
                             : "r"(addr));
            }
#pragma unroll
            for (int mi = 0; mi < 2; mi++)
#pragma unroll
                for (int ni = 0; ni < 4; ni++) {
                    asm volatile(
                        "mma.sync.aligned.m16n8k16.row.col.f32.bf16.bf16.f32 "
                        "{%0,%1,%2,%3}, {%4,%5,%6,%7}, {%8,%9}, {%0,%1,%2,%3};"
                        : "+f"(acc[mi][ni*2][0]), "+f"(acc[mi][ni*2][1]),
                          "+f"(acc[mi][ni*2][2]), "+f"(acc[mi][ni*2][3])
                        : "r"(af[mi][0]), "r"(af[mi][1]), "r"(af[mi][2]), "r"(af[mi][3]),
                          "r"(bf[ni][0]), "r"(bf[ni][1]));
                    asm volatile(
                        "mma.sync.aligned.m16n8k16.row.col.f32.bf16.bf16.f32 "
                        "{%0,%1,%2,%3}, {%4,%5,%6,%7}, {%8,%9}, {%0,%1,%2,%3};"
                        : "+f"(acc[mi][ni*2+1][0]), "+f"(acc[mi][ni*2+1][1]),
                          "+f"(acc[mi][ni*2+1][2]), "+f"(acc[mi][ni*2+1][3])
                        : "r"(af[mi][0]), "r"(af[mi][1]), "r"(af[mi][2]), "r"(af[mi][3]),
                          "r"(bf[ni][2]), "r"(bf[ni][3]));
                }
        }
    }

    // ---- epilogue ----
    const float* bias = mat ? bdst : bsrc;
    float* outp       = mat ? g_fd : g_fs;
    const int g  = lane >> 2;
    const int tg = lane & 3;
#pragma unroll
    for (int mi = 0; mi < 2; mi++) {
#pragma unroll
        for (int n8 = 0; n8 < 8; n8++) {
            int colg = nh * 128 + nbase + n8 * 8 + tg * 2;
            float b0 = __ldg(bias + colg);
            float b1 = __ldg(bias + colg + 1);
            int r1 = row0 + mbase + mi * 16 + g;
            int r2 = r1 + 8;
            if (r1 < N_NODES) {
                float2 v = make_float2(acc[mi][n8][0] + b0, acc[mi][n8][1] + b1);
                *(float2*)(outp + (size_t)r1 * HD + colg) = v;
            }
            if (r2 < N_NODES) {
                float2 v = make_float2(acc[mi][n8][2] + b0, acc[mi][n8][3] + b1);
                *(float2*)(outp + (size_t)r2 * HD + colg) = v;
            }
        }
    }
}

// ---------------- CSR build ----------------
__global__ __launch_bounds__(256) void k_hist(const int* __restrict__ dst) {
    int e = blockIdx.x * blockDim.x + threadIdx.x;
    if (e < N_EDGES) atomicAdd(&g_deg[dst[e]], 1);
}

__global__ __launch_bounds__(256) void k_scan1() {
    __shared__ int sh[256];
    int i = blockIdx.x * 256 + threadIdx.x;
    int v = (i < N_NODES) ? g_deg[i] : 0;
    sh[threadIdx.x] = v;
    __syncthreads();
    for (int d = 1; d < 256; d <<= 1) {
        int t = (threadIdx.x >= d) ? sh[threadIdx.x - d] : 0;
        __syncthreads();
        sh[threadIdx.x] += t;
        __syncthreads();
    }
    if (threadIdx.x == 255) g_blksum[blockIdx.x] = sh[255];
}

__global__ __launch_bounds__(256) void k_scan2() {
    __shared__ int sh[256];
    int v = (threadIdx.x < SCAN_NB) ? g_blksum[threadIdx.x] : 0;
    sh[threadIdx.x] = v;
    __syncthreads();
    for (int d = 1; d < 256; d <<= 1) {
        int t = (threadIdx.x >= d) ? sh[threadIdx.x - d] : 0;
        __syncthreads();
        sh[threadIdx.x] += t;
        __syncthreads();
    }
    if (threadIdx.x < SCAN_NB) g_blksum[threadIdx.x] = sh[threadIdx.x] - v;  // exclusive
}

__global__ __launch_bounds__(256) void k_scan3() {
    __shared__ int sh[256];
    int i = blockIdx.x * 256 + threadIdx.x;
    int v = (i < N_NODES) ? g_deg[i] : 0;
    sh[threadIdx.x] = v;
    __syncthreads();
    for (int d = 1; d < 256; d <<= 1) {
        int t = (threadIdx.x >= d) ? sh[threadIdx.x - d] : 0;
        __syncthreads();
        sh[threadIdx.x] += t;
        __syncthreads();
    }
    if (i < N_NODES) g_off[i] = g_blksum[blockIdx.x] + sh[threadIdx.x] - v;
}

__global__ __launch_bounds__(256) void k_fill(const int* __restrict__ dst) {
    int e = blockIdx.x * blockDim.x + threadIdx.x;
    if (e >= N_EDGES) return;
    int d = dst[e];
    int pos = atomicAdd(&g_cur[d], 1);
    g_eid[g_off[d] + pos] = e;
}

// ---------------- fused per-node online-softmax aggregation ----------------
__global__ __launch_bounds__(256) void k_agg(
    const int* __restrict__ src, const float* __restrict__ attn,
    const int* __restrict__ gid, float* __restrict__ x1)
{
    int warp = (blockIdx.x * blockDim.x + threadIdx.x) >> 5;
    if (warp >= N_NODES) return;
    int n = warp;
    int lane = threadIdx.x & 31;
    int base = lane * 8;
    int h = lane >> 3;

    float4 fd0 = *(const float4*)(g_fd + (size_t)n * HD + base);
    float4 fd1 = *(const float4*)(g_fd + (size_t)n * HD + base + 4);
    float4 aw0 = __ldg((const float4*)(attn + base));
    float4 aw1 = __ldg((const float4*)(attn + base + 4));

    int deg = g_deg[n];
    int off = g_off[n];

    float m = __int_as_float(0xff800000);
    float den = 0.0f;
    float acc[8];
#pragma unroll
    for (int j = 0; j < 8; j++) acc[j] = 0.0f;

    for (int i = 0; i < deg; i++) {
        int e_id = g_eid[off + i];
        int s = src[e_id];
        const float4* pfs = (const float4*)(g_fs + (size_t)s * HD + base);
        float4 a0 = pfs[0], a1 = pfs[1];

        float e_val;
        e_val  = lrelu(a0.x + fd0.x) * aw0.x;
        e_val += lrelu(a0.y + fd0.y) * aw0.y;
        e_val += lrelu(a0.z + fd0.z) * aw0.z;
        e_val += lrelu(a0.w + fd0.w) * aw0.w;
        e_val += lrelu(a1.x + fd1.x) * aw1.x;
        e_val += lrelu(a1.y + fd1.y) * aw1.y;
        e_val += lrelu(a1.z + fd1.z) * aw1.z;
        e_val += lrelu(a1.w + fd1.w) * aw1.w;
        e_val += __shfl_xor_sync(0xFFFFFFFFu, e_val, 1);
        e_val += __shfl_xor_sync(0xFFFFFFFFu, e_val, 2);
        e_val += __shfl_xor_sync(0xFFFFFFFFu, e_val, 4);

        if ((lane & 7) == 0)
            g_e[(size_t)e_id * HEADS + h] = e_val;

        float m_new = fmaxf(m, e_val);
        float scale = expf(m - m_new);
        float ex    = expf(e_val - m_new);
        den = den * scale + ex;
        acc[0] = acc[0] * scale + ex * a0.x;
        acc[1] = acc[1] * scale + ex * a0.y;
        acc[2] = acc[2] * scale + ex * a0.z;
        acc[3] = acc[3] * scale + ex * a0.w;
        acc[4] = acc[4] * scale + ex * a1.x;
        acc[5] = acc[5] * scale + ex * a1.y;
        acc[6] = acc[6] * scale + ex * a1.z;
        acc[7] = acc[7] * scale + ex * a1.w;
        m = m_new;
    }

    if (deg > 0 && (lane & 7) == 0) {
        g_m  [n * HEADS + h] = m;
        g_den[n * HEADS + h] = den;
    }

    float inv = (den > 0.0f) ? (1.0f / den) : 0.0f;
    float r[8];
#pragma unroll
    for (int j = 0; j < 8; j++) {
        r[j] = acc[j] * inv;
        r[j] += __shfl_xor_sync(0xFFFFFFFFu, r[j], 8);
        r[j] += __shfl_xor_sync(0xFFFFFFFFu, r[j], 16);
        r[j] *= 0.25f;
    }

    int g = gid[n];
    if (lane < 8) {
        float4 v0 = make_float4(r[0], r[1], r[2], r[3]);
        float4 v1 = make_float4(r[4], r[5], r[6], r[7]);
        float* xp = x1 + (size_t)n * DIM + lane * 8;
        *(float4*)(xp)     = v0;
        *(float4*)(xp + 4) = v1;
        atomicAdd((float4*)(g_hsum + (size_t)g * DIM + lane * 8),     v0);
        atomicAdd((float4*)(g_hsum + (size_t)g * DIM + lane * 8 + 4), v1);
    }
    if (lane == 0) atomicAdd(&g_cnt[g], 1.0f);
}

// ---------------- score ----------------
__global__ __launch_bounds__(256) void k_score(
    const int* __restrict__ dst, float* __restrict__ score)
{
    int idx = blockIdx.x * blockDim.x + threadIdx.x;
    if (idx >= N_EDGES * HEADS) return;
    int e = idx >> 2, h = idx & 3;
    int d = dst[e];
    float alpha = expf(g_e[idx] - g_m[d * HEADS + h]) / g_den[d * HEADS + h];
    score[idx] = alpha;
}

// ---------------- graph mean finalize ----------------
__global__ __launch_bounds__(256) void k_final(float* __restrict__ hout)
{
    int idx = blockIdx.x * blockDim.x + threadIdx.x;
    if (idx >= NGRAPHS * DIM) return;
    int g = idx >> 6;
    hout[idx] = g_hsum[idx] / fmaxf(g_cnt[g], 1.0f);
}

// ---------------- launcher ----------------
extern "C" void kernel_launch(void* const* d_in, const int* in_sizes, int n_in,
                              void* d_out, int out_size)
{
    (void)in_sizes; (void)n_in; (void)out_size;

    const float* atom = (const float*)d_in[0];
    const float* Wsrc = (const float*)d_in[1];
    const float* bsrc = (const float*)d_in[2];
    const float* Wdst = (const float*)d_in[3];
    const float* bdst = (const float*)d_in[4];
    const float* attn = (const float*)d_in[5];
    const int*   src  = (const int*)d_in[6];
    const int*   dst  = (const int*)d_in[7];
    const int*   gid  = (const int*)d_in[8];

    float* out   = (float*)d_out;
    float* x1    = out;
    float* hout  = out + (size_t)N_NODES * DIM;
    float* score = hout + (size_t)NGRAPHS * DIM;

    cudaFuncSetAttribute(k_mgemm, cudaFuncAttributeMaxDynamicSharedMemorySize, SM_TOT);

    k_init<<<256, 256>>>();
    k_prepB<<<(2 * KEXT * HD + 255) / 256, 256>>>(Wsrc, Wdst);

    dim3 ggrid((N_NODES + 127) / 128, 4);
    k_mgemm<<<ggrid, 256, SM_TOT>>>(atom, bsrc, bdst);

    int eblocks = (N_EDGES + 255) / 256;
    k_hist<<<eblocks, 256>>>(dst);
    k_scan1<<<SCAN_NB, 256>>>();
    k_scan2<<<1, 256>>>();
    k_scan3<<<SCAN_NB, 256>>>();
    k_fill<<<eblocks, 256>>>(dst);

    k_agg<<<(N_NODES * 32 + 255) / 256, 256>>>(src, attn, gid, x1);

    k_score<<<(N_EDGES * HEADS + 255) / 256, 256>>>(dst, score);

    k_final<<<(NGRAPHS * DIM + 255) / 256, 256>>>(hout);
}

// round 8
// speedup vs baseline: 2.6498x; 1.2219x over previous
#include <cuda_runtime.h>
#include <cuda_bf16.h>
#include <cstdint>

// ---------------- problem constants ----------------
#define N_NODES  50000
#define N_EDGES  400000
#define IN_F     128
#define HEADS    4
#define DIM      64
#define HD       256           // HEADS*DIM
#define NGRAPHS  2000
#define NEG_SLOPE 0.2f
#define SCAN_NB  196           // ceil(50000/256)
#define KEXT     384           // 3 * IN_F (bf16 split terms)

// ---------------- device scratch ----------------
__device__ float g_fs[(size_t)N_NODES * HD];
__device__ float g_fd[(size_t)N_NODES * HD];
__device__ float g_e [(size_t)N_EDGES * HEADS];
__device__ float g_m [N_NODES * HEADS];
__device__ float g_den[N_NODES * HEADS];
__device__ float g_hsum[NGRAPHS * DIM];
__device__ float g_cnt [NGRAPHS];
__device__ int   g_deg[N_NODES];
__device__ int   g_cur[N_NODES];
__device__ int   g_off[N_NODES];
__device__ int2  g_epack[N_EDGES];        // {edge_id, src}
__device__ int   g_blksum[SCAN_NB];
__device__ __align__(16) __nv_bfloat16 g_Bext[2 * KEXT * HD];

__device__ __forceinline__ float lrelu(float x) {
    return x > 0.0f ? x : NEG_SLOPE * x;
}

__device__ __forceinline__ uint32_t smem_u32(const void* p) {
    uint32_t a;
    asm("{ .reg .u64 t; cvta.to.shared.u64 t, %1; cvt.u32.u64 %0, t; }" : "=r"(a) : "l"(p));
    return a;
}

// A smem: 128 rows x 256 bf16 cols (hi | lo), 512 B/row
__device__ __forceinline__ uint32_t a_off(int r, int c) {
    int chunk = (c >> 3) ^ (r & 7);
    return (uint32_t)r * 512u + (uint32_t)chunk * 16u + (uint32_t)(c & 7) * 2u;
}
// B smem: 32 k-rows x 256 bf16 cols, 512 B/row
__device__ __forceinline__ uint32_t b_off(int k, int n) {
    int chunk = (n >> 3) ^ (k & 7);
    return (uint32_t)k * 512u + (uint32_t)chunk * 16u + (uint32_t)(n & 7) * 2u;
}

// ---------------- fused prologue: zero scratch + build B_ext ----------------
__global__ __launch_bounds__(256) void k_pre(
    const float* __restrict__ Wsrc, const float* __restrict__ Wdst)
{
    int i = blockIdx.x * blockDim.x + threadIdx.x;
    int stride = gridDim.x * blockDim.x;
    for (int j = i; j < NGRAPHS * DIM; j += stride) g_hsum[j] = 0.0f;
    for (int j = i; j < NGRAPHS; j += stride) g_cnt[j] = 0.0f;
    for (int j = i; j < N_NODES; j += stride) { g_deg[j] = 0; g_cur[j] = 0; }
    for (int j = i; j < 2 * KEXT * HD; j += stride) {
        int mat  = j / (KEXT * HD);
        int r    = j % (KEXT * HD);
        int kext = r >> 8;
        int n    = r & 255;
        int k    = (kext < 2 * IN_F) ? (kext & (IN_F - 1)) : (kext - 2 * IN_F);
        const float* W = mat ? Wdst : Wsrc;
        float v = W[(size_t)k * HD + n];
        __nv_bfloat16 hi = __float2bfloat16(v);
        g_Bext[j] = (kext < 2 * IN_F) ? hi : __float2bfloat16(v - __bfloat162float(hi));
    }
}

__global__ __launch_bounds__(256) void k_hist(const int* __restrict__ dst) {
    int e = blockIdx.x * blockDim.x + threadIdx.x;
    if (e < N_EDGES) atomicAdd(&g_deg[dst[e]], 1);
}

// ---------------- bf16 mma.sync GEMM, A reused across both matrices ----------------
// block 512 thr, tile 128(M) x 256(N); mat loop inside; grid = 391
#define SM_A_BYTES 65536
#define SM_B_BYTES 16384
#define SM_TOT (SM_A_BYTES + SM_B_BYTES)

__global__ __launch_bounds__(512) void k_mgemm(
    const float* __restrict__ atom,
    const float* __restrict__ bsrc, const float* __restrict__ bdst)
{
    extern __shared__ char smem[];
    const uint32_t sA = smem_u32(smem);
    const uint32_t sB = sA + SM_A_BYTES;

    const int tid  = threadIdx.x;
    const int lane = tid & 31;
    const int wid  = tid >> 5;             // 0..15
    const int row0 = blockIdx.x * 128;

    // ---- A: load 128 rows x 128 fp32 once, hi/lo bf16 into smem ----
    {
        int ar = tid >> 2;                 // 0..127
        int c0 = (tid & 3) * 32;
        bool valid = (row0 + ar) < N_NODES;
        const float4* arow = (const float4*)(atom + (size_t)(row0 + ar) * IN_F + c0);
#pragma unroll
        for (int i = 0; i < 8; i++) {
            float4 v = valid ? arow[i] : make_float4(0.f, 0.f, 0.f, 0.f);
            int c = c0 + i * 4;
            __nv_bfloat162 h0 = __float22bfloat162_rn(make_float2(v.x, v.y));
            __nv_bfloat162 h1 = __float22bfloat162_rn(make_float2(v.z, v.w));
            float2 f0 = __bfloat1622float2(h0);
            float2 f1 = __bfloat1622float2(h1);
            __nv_bfloat162 l0 = __float22bfloat162_rn(make_float2(v.x - f0.x, v.y - f0.y));
            __nv_bfloat162 l1 = __float22bfloat162_rn(make_float2(v.z - f1.x, v.w - f1.y));
            uint2 hp, lp;
            hp.x = *(uint32_t*)&h0; hp.y = *(uint32_t*)&h1;
            lp.x = *(uint32_t*)&l0; lp.y = *(uint32_t*)&l1;
            *(uint2*)(smem + a_off(ar, c))       = hp;
            *(uint2*)(smem + a_off(ar, 128 + c)) = lp;
        }
    }

    // ---- warp tiling: 4x4 warp grid, each 32(M) x 64(N) ----
    const int wr = wid >> 2;               // 0..3
    const int wc = wid & 3;                // 0..3
    const int mbase = wr * 32;
    const int nbase = wc * 64;

    // B staging: 32 k-rows x 256 cols = 16 KB; 512 thr x 32 B
    const int kr = tid >> 4;               // 0..31
    const int ch = tid & 15;               // 0..15
    const uint32_t bso0 = SM_A_BYTES + b_off(kr, ch * 8);
    const uint32_t bso1 = SM_A_BYTES + b_off(kr, 128 + ch * 8);

    // ldmatrix lane addressing
    const int a_r  = lane & 15;
    const int a_c8 = (lane >> 4) << 3;
    const int b_kr = (lane & 7) + (((lane >> 3) & 1) << 3);
    const int b_n8 = (lane >> 4) << 3;

    const int g  = lane >> 2;
    const int tg = lane & 3;

    for (int mat = 0; mat < 2; mat++) {
        const __nv_bfloat16* Bg = g_Bext + (size_t)mat * KEXT * HD;

        float acc[2][8][4];
#pragma unroll
        for (int a = 0; a < 2; a++)
#pragma unroll
            for (int b = 0; b < 8; b++)
#pragma unroll
                for (int c = 0; c < 4; c++) acc[a][b][c] = 0.0f;

        // prefetch iteration 0
        uint4 pv0 = *(const uint4*)(Bg + (size_t)kr * HD + ch * 8);
        uint4 pv1 = *(const uint4*)(Bg + (size_t)kr * HD + 128 + ch * 8);

        for (int it = 0; it < 12; it++) {
            __syncthreads();               // prev smem reads done (covers A build / prev mat too)
            *(uint4*)(smem + bso0) = pv0;
            *(uint4*)(smem + bso1) = pv1;
            __syncthreads();               // B tile ready

            if (it < 11) {                 // prefetch next chunk; latency overlaps MMA below
                const __nv_bfloat16* brow = Bg + (size_t)((it + 1) * 32 + kr) * HD;
                pv0 = *(const uint4*)(brow + ch * 8);
                pv1 = *(const uint4*)(brow + 128 + ch * 8);
            }

            const int kk = it * 32;
            const int term = kk >> 7;
            const int acolb = (term == 1) ? (128 + (kk & 127)) : (kk & 127);

#pragma unroll
            for (int ks = 0; ks < 32; ks += 16) {
                uint32_t af[2][4];
#pragma unroll
                for (int mi = 0; mi < 2; mi++) {
                    uint32_t addr = sA + a_off(mbase + mi * 16 + a_r, acolb + ks + a_c8);
                    asm volatile("ldmatrix.sync.aligned.m8n8.x4.shared.b16 {%0,%1,%2,%3}, [%4];"
                                 : "=r"(af[mi][0]), "=r"(af[mi][1]), "=r"(af[mi][2]), "=r"(af[mi][3])
                                 : "r"(addr));
                }
                uint32_t bf[4][4];
#pragma unroll
                for (int ni = 0; ni < 4; ni++) {
                    uint32_t addr = sB + b_off(ks + b_kr, nbase + ni * 16 + b_n8);
                    asm volatile("ldmatrix.sync.aligned.m8n8.x4.trans.shared.b16 {%0,%1,%2,%3}, [%4];"
                                 : "=r"(bf[ni][0]), "=r"(bf[ni][1]), "=r"(bf[ni][2]), "=r"(bf[ni][3])
                                 : "r"(addr));
                }
#pragma unroll
                for (int mi = 0; mi < 2; mi++)
#pragma unroll
                    for (int ni = 0; ni < 4; ni++) {
                        asm volatile(
                            "mma.sync.aligned.m16n8k16.row.col.f32.bf16.bf16.f32 "
                            "{%0,%1,%2,%3}, {%4,%5,%6,%7}, {%8,%9}, {%0,%1,%2,%3};"
                            : "+f"(acc[mi][ni*2][0]), "+f"(acc[mi][ni*2][1]),
                              "+f"(acc[mi][ni*2][2]), "+f"(acc[mi][ni*2][3])
                            : "r"(af[mi][0]), "r"(af[mi][1]), "r"(af[mi][2]), "r"(af[mi][3]),
                              "r"(bf[ni][0]), "r"(bf[ni][1]));
                        asm volatile(
                            "mma.sync.aligned.m16n8k16.row.col.f32.bf16.bf16.f32 "
                            "{%0,%1,%2,%3}, {%4,%5,%6,%7}, {%8,%9}, {%0,%1,%2,%3};"
                            : "+f"(acc[mi][ni*2+1][0]), "+f"(acc[mi][ni*2+1][1]),
                              "+f"(acc[mi][ni*2+1][2]), "+f"(acc[mi][ni*2+1][3])
                            : "r"(af[mi][0]), "r"(af[mi][1]), "r"(af[mi][2]), "r"(af[mi][3]),
                              "r"(bf[ni][2]), "r"(bf[ni][3]));
                    }
            }
        }

        // ---- epilogue for this mat ----
        const float* bias = mat ? bdst : bsrc;
        float* outp       = mat ? g_fd : g_fs;
#pragma unroll
        for (int mi = 0; mi < 2; mi++) {
#pragma unroll
            for (int n8 = 0; n8 < 8; n8++) {
                int colg = nbase + n8 * 8 + tg * 2;
                float b0 = __ldg(bias + colg);
                float b1 = __ldg(bias + colg + 1);
                int r1 = row0 + mbase + mi * 16 + g;
                int r2 = r1 + 8;
                if (r1 < N_NODES) {
                    float2 v = make_float2(acc[mi][n8][0] + b0, acc[mi][n8][1] + b1);
                    *(float2*)(outp + (size_t)r1 * HD + colg) = v;
                }
                if (r2 < N_NODES) {
                    float2 v = make_float2(acc[mi][n8][2] + b0, acc[mi][n8][3] + b1);
                    *(float2*)(outp + (size_t)r2 * HD + colg) = v;
                }
            }
        }
    }
}

// ---------------- scans ----------------
__global__ __launch_bounds__(256) void k_scan1() {
    __shared__ int sh[256];
    int i = blockIdx.x * 256 + threadIdx.x;
    int v = (i < N_NODES) ? g_deg[i] : 0;
    sh[threadIdx.x] = v;
    __syncthreads();
    for (int d = 1; d < 256; d <<= 1) {
        int t = (threadIdx.x >= d) ? sh[threadIdx.x - d] : 0;
        __syncthreads();
        sh[threadIdx.x] += t;
        __syncthreads();
    }
    if (threadIdx.x == 255) g_blksum[blockIdx.x] = sh[255];
}

__global__ __launch_bounds__(256) void k_scan2() {
    __shared__ int sh[256];
    int v = (threadIdx.x < SCAN_NB) ? g_blksum[threadIdx.x] : 0;
    sh[threadIdx.x] = v;
    __syncthreads();
    for (int d = 1; d < 256; d <<= 1) {
        int t = (threadIdx.x >= d) ? sh[threadIdx.x - d] : 0;
        __syncthreads();
        sh[threadIdx.x] += t;
        __syncthreads();
    }
    if (threadIdx.x < SCAN_NB) g_blksum[threadIdx.x] = sh[threadIdx.x] - v;
}

__global__ __launch_bounds__(256) void k_scan3() {
    __shared__ int sh[256];
    int i = blockIdx.x * 256 + threadIdx.x;
    int v = (i < N_NODES) ? g_deg[i] : 0;
    sh[threadIdx.x] = v;
    __syncthreads();
    for (int d = 1; d < 256; d <<= 1) {
        int t = (threadIdx.x >= d) ? sh[threadIdx.x - d] : 0;
        __syncthreads();
        sh[threadIdx.x] += t;
        __syncthreads();
    }
    if (i < N_NODES) g_off[i] = g_blksum[blockIdx.x] + sh[threadIdx.x] - v;
}

__global__ __launch_bounds__(256) void k_fill(
    const int* __restrict__ dst, const int* __restrict__ src)
{
    int e = blockIdx.x * blockDim.x + threadIdx.x;
    if (e >= N_EDGES) return;
    int d = dst[e];
    int pos = atomicAdd(&g_cur[d], 1);
    g_epack[g_off[d] + pos] = make_int2(e, src[e]);
}

// ---------------- fused per-node online-softmax aggregation ----------------
__global__ __launch_bounds__(256) void k_agg(
    const float* __restrict__ attn,
    const int* __restrict__ gid, float* __restrict__ x1)
{
    int warp = (blockIdx.x * blockDim.x + threadIdx.x) >> 5;
    if (warp >= N_NODES) return;
    int n = warp;
    int lane = threadIdx.x & 31;
    int base = lane * 8;
    int h = lane >> 3;

    float4 fd0 = *(const float4*)(g_fd + (size_t)n * HD + base);
    float4 fd1 = *(const float4*)(g_fd + (size_t)n * HD + base + 4);
    float4 aw0 = __ldg((const float4*)(attn + base));
    float4 aw1 = __ldg((const float4*)(attn + base + 4));

    int deg = g_deg[n];
    int off = g_off[n];

    float m = __int_as_float(0xff800000);
    float den = 0.0f;
    float acc[8];
#pragma unroll
    for (int j = 0; j < 8; j++) acc[j] = 0.0f;

    for (int i = 0; i < deg; i++) {
        int2 es = g_epack[off + i];
        const float4* pfs = (const float4*)(g_fs + (size_t)es.y * HD + base);
        float4 a0 = pfs[0], a1 = pfs[1];

        float e_val;
        e_val  = lrelu(a0.x + fd0.x) * aw0.x;
        e_val += lrelu(a0.y + fd0.y) * aw0.y;
        e_val += lrelu(a0.z + fd0.z) * aw0.z;
        e_val += lrelu(a0.w + fd0.w) * aw0.w;
        e_val += lrelu(a1.x + fd1.x) * aw1.x;
        e_val += lrelu(a1.y + fd1.y) * aw1.y;
        e_val += lrelu(a1.z + fd1.z) * aw1.z;
        e_val += lrelu(a1.w + fd1.w) * aw1.w;
        e_val += __shfl_xor_sync(0xFFFFFFFFu, e_val, 1);
        e_val += __shfl_xor_sync(0xFFFFFFFFu, e_val, 2);
        e_val += __shfl_xor_sync(0xFFFFFFFFu, e_val, 4);

        if ((lane & 7) == 0)
            g_e[(size_t)es.x * HEADS + h] = e_val;

        float m_new = fmaxf(m, e_val);
        float scale = expf(m - m_new);
        float ex    = expf(e_val - m_new);
        den = den * scale + ex;
        acc[0] = acc[0] * scale + ex * a0.x;
        acc[1] = acc[1] * scale + ex * a0.y;
        acc[2] = acc[2] * scale + ex * a0.z;
        acc[3] = acc[3] * scale + ex * a0.w;
        acc[4] = acc[4] * scale + ex * a1.x;
        acc[5] = acc[5] * scale + ex * a1.y;
        acc[6] = acc[6] * scale + ex * a1.z;
        acc[7] = acc[7] * scale + ex * a1.w;
        m = m_new;
    }

    if (deg > 0 && (lane & 7) == 0) {
        g_m  [n * HEADS + h] = m;
        g_den[n * HEADS + h] = den;
    }

    float inv = (den > 0.0f) ? (1.0f / den) : 0.0f;
    float r[8];
#pragma unroll
    for (int j = 0; j < 8; j++) {
        r[j] = acc[j] * inv;
        r[j] += __shfl_xor_sync(0xFFFFFFFFu, r[j], 8);
        r[j] += __shfl_xor_sync(0xFFFFFFFFu, r[j], 16);
        r[j] *= 0.25f;
    }

    int g = gid[n];
    if (lane < 8) {
        float4 v0 = make_float4(r[0], r[1], r[2], r[3]);
        float4 v1 = make_float4(r[4], r[5], r[6], r[7]);
        float* xp = x1 + (size_t)n * DIM + lane * 8;
        *(float4*)(xp)     = v0;
        *(float4*)(xp + 4) = v1;
        atomicAdd((float4*)(g_hsum + (size_t)g * DIM + lane * 8),     v0);
        atomicAdd((float4*)(g_hsum + (size_t)g * DIM + lane * 8 + 4), v1);
    }
    if (lane == 0) atomicAdd(&g_cnt[g], 1.0f);
}

// ---------------- score ----------------
__global__ __launch_bounds__(256) void k_score(
    const int* __restrict__ dst, float* __restrict__ score)
{
    int idx = blockIdx.x * blockDim.x + threadIdx.x;
    if (idx >= N_EDGES * HEADS) return;
    int e = idx >> 2, h = idx & 3;
    int d = dst[e];
    float alpha = expf(g_e[idx] - g_m[d * HEADS + h]) / g_den[d * HEADS + h];
    score[idx] = alpha;
}

// ---------------- graph mean finalize ----------------
__global__ __launch_bounds__(256) void k_final(float* __restrict__ hout)
{
    int idx = blockIdx.x * blockDim.x + threadIdx.x;
    if (idx >= NGRAPHS * DIM) return;
    int g = idx >> 6;
    hout[idx] = g_hsum[idx] / fmaxf(g_cnt[g], 1.0f);
}

// ---------------- launcher ----------------
extern "C" void kernel_launch(void* const* d_in, const int* in_sizes, int n_in,
                              void* d_out, int out_size)
{
    (void)in_sizes; (void)n_in; (void)out_size;

    const float* atom = (const float*)d_in[0];
    const float* Wsrc = (const float*)d_in[1];
    const float* bsrc = (const float*)d_in[2];
    const float* Wdst = (const float*)d_in[3];
    const float* bdst = (const float*)d_in[4];
    const float* attn = (const float*)d_in[5];
    const int*   src  = (const int*)d_in[6];
    const int*   dst  = (const int*)d_in[7];
    const int*   gid  = (const int*)d_in[8];

    float* out   = (float*)d_out;
    float* x1    = out;
    float* hout  = out + (size_t)N_NODES * DIM;
    float* score = hout + (size_t)NGRAPHS * DIM;

    cudaFuncSetAttribute(k_mgemm, cudaFuncAttributeMaxDynamicSharedMemorySize, SM_TOT);

    k_pre<<<512, 256>>>(Wsrc, Wdst);                      // zero + B_ext

    int eblocks = (N_EDGES + 255) / 256;
    k_hist<<<eblocks, 256>>>(dst);                        // needs zeroed g_deg

    k_mgemm<<<(N_NODES + 127) / 128, 512, SM_TOT>>>(atom, bsrc, bdst);

    k_scan1<<<SCAN_NB, 256>>>();
    k_scan2<<<1, 256>>>();
    k_scan3<<<SCAN_NB, 256>>>();
    k_fill<<<eblocks, 256>>>(dst, src);

    k_agg<<<(N_NODES * 32 + 255) / 256, 256>>>(attn, gid, x1);

    k_score<<<(N_EDGES * HEADS + 255) / 256, 256>>>(dst, score);

    k_final<<<(NGRAPHS * DIM + 255) / 256, 256>>>(hout);
}